// round 14
// baseline (speedup 1.0000x reference)
#include <cuda_runtime.h>
#include <cuda_bf16.h>

// Problem constants
#define N_DET   20000
#define IN_DIM  151
#define HID_DIM 256
#define OUT_DIM 128
#define IN_P    80       // k-pairs for IN_DIM (76 real, 4 zero) -> 5 stages of 16
#define HID_P   128      // k-pairs for HID_DIM -> 8 stages of 16
#define IN_E    160      // padded elements

typedef unsigned short ushort_t;

// Scratch (allocation forbidden -> __device__ globals)
__device__ __align__(16) float    g_S[N_DET * OUT_DIM];
__device__ __align__(16) float    g_O[N_DET * OUT_DIM];
__device__ __align__(16) unsigned g_Xp_hi[N_DET * IN_P];       // pair-packed rows
__device__ __align__(16) unsigned g_Xp_lo[N_DET * IN_P];
__device__ __align__(16) unsigned g_Hp_hi[2][N_DET * HID_P];   // pair-packed H
__device__ __align__(16) unsigned g_Hp_lo[2][N_DET * HID_P];
__device__ __align__(16) ushort_t g_W1e_hi[2][IN_E * HID_DIM]; // element [k][n]
__device__ __align__(16) ushort_t g_W1e_lo[2][IN_E * HID_DIM];
__device__ __align__(16) ushort_t g_W2e_hi[2][HID_DIM * OUT_DIM];
__device__ __align__(16) ushort_t g_W2e_lo[2][HID_DIM * OUT_DIM];
__device__ int g_idx64;

// ---------------------------------------------------------------------------
__global__ void probe_dtype(const long long* __restrict__ e)
{
    bool ok64 = true;
    for (int i = 0; i < 48; i++) {
        long long v = e[i];
        if (v < 0 || v >= N_DET) ok64 = false;
    }
    g_idx64 = ok64 ? 1 : 0;
}

// ---------------------------------------------------------------------------
// bf16 helpers
// ---------------------------------------------------------------------------
__device__ __forceinline__ void split_bf16(float v, ushort_t& hi, ushort_t& lo)
{
    __nv_bfloat16 h = __float2bfloat16(v);
    __nv_bfloat16 l = __float2bfloat16(v - __bfloat162float(h));
    hi = __bfloat16_as_ushort(h);
    lo = __bfloat16_as_ushort(l);
}
__device__ __forceinline__ unsigned pack2(ushort_t a, ushort_t b)
{
    return (unsigned)a | ((unsigned)b << 16);
}
__device__ __forceinline__ void split_pair(float v0, float v1, unsigned& hi, unsigned& lo)
{
    ushort_t h0, l0, h1, l1;
    split_bf16(v0, h0, l0);
    split_bf16(v1, h1, l1);
    hi = pack2(h0, h1);
    lo = pack2(l0, l1);
}

__device__ __forceinline__ void mma_bf16(float* d, const unsigned* a, const unsigned* b)
{
    asm("mma.sync.aligned.m16n8k16.row.col.f32.bf16.bf16.f32 "
        "{%0,%1,%2,%3}, {%4,%5,%6,%7}, {%8,%9}, {%0,%1,%2,%3};"
        : "+f"(d[0]), "+f"(d[1]), "+f"(d[2]), "+f"(d[3])
        : "r"(a[0]), "r"(a[1]), "r"(a[2]), "r"(a[3]), "r"(b[0]), "r"(b[1]));
}

__device__ __forceinline__ void ldsm_x4(unsigned* r, const void* p)
{
    unsigned a = (unsigned)__cvta_generic_to_shared(p);
    asm volatile("ldmatrix.sync.aligned.m8n8.x4.shared.b16 {%0,%1,%2,%3}, [%4];"
                 : "=r"(r[0]), "=r"(r[1]), "=r"(r[2]), "=r"(r[3]) : "r"(a));
}
__device__ __forceinline__ void ldsm_x4_t(unsigned* r, const void* p)
{
    unsigned a = (unsigned)__cvta_generic_to_shared(p);
    asm volatile("ldmatrix.sync.aligned.m8n8.x4.trans.shared.b16 {%0,%1,%2,%3}, [%4];"
                 : "=r"(r[0]), "=r"(r[1]), "=r"(r[2]), "=r"(r[3]) : "r"(a));
}

// cp.async 16B global->shared
__device__ __forceinline__ void cp16(const void* dst, const void* src)
{
    unsigned d = (unsigned)__cvta_generic_to_shared(dst);
    asm volatile("cp.async.cg.shared.global [%0], [%1], 16;" :: "r"(d), "l"(src));
}

// ---------------------------------------------------------------------------
// Prep kernels
// ---------------------------------------------------------------------------
__global__ void prep_X(const float* __restrict__ X)
{
    int idx = blockIdx.x * blockDim.x + threadIdx.x;
    if (idx >= N_DET * IN_P) return;
    int row = idx / IN_P, j = idx - row * IN_P;
    float v0 = (2 * j     < IN_DIM) ? X[(size_t)row * IN_DIM + 2 * j]     : 0.f;
    float v1 = (2 * j + 1 < IN_DIM) ? X[(size_t)row * IN_DIM + 2 * j + 1] : 0.f;
    unsigned hi, lo;
    split_pair(v0, v1, hi, lo);
    g_Xp_hi[idx] = hi;
    g_Xp_lo[idx] = lo;
}

__global__ void prep_W(const float* __restrict__ Ws_w1, const float* __restrict__ Wo_w1,
                       const float* __restrict__ Ws_w2, const float* __restrict__ Wo_w2)
{
    int idx = blockIdx.x * blockDim.x + threadIdx.x;
    const int W1TOT = 2 * IN_E * HID_DIM;     // 81920
    const int W2TOT = 2 * HID_DIM * OUT_DIM;  // 65536
    if (idx < W1TOT) {
        int net = idx / (IN_E * HID_DIM);
        int r = idx - net * (IN_E * HID_DIM);
        int k = r / HID_DIM, n = r - k * HID_DIM;
        const float* W = net ? Wo_w1 : Ws_w1;
        float v = (k < IN_DIM) ? W[(size_t)k * HID_DIM + n] : 0.f;
        ushort_t hi, lo;
        split_bf16(v, hi, lo);
        g_W1e_hi[net][r] = hi;
        g_W1e_lo[net][r] = lo;
    } else if (idx < W1TOT + W2TOT) {
        int j = idx - W1TOT;
        int net = j / (HID_DIM * OUT_DIM);
        int r = j - net * (HID_DIM * OUT_DIM);
        float v = (net ? Wo_w2 : Ws_w2)[r];
        ushort_t hi, lo;
        split_bf16(v, hi, lo);
        g_W2e_hi[net][r] = hi;
        g_W2e_lo[net][r] = lo;
    }
}

// ---------------------------------------------------------------------------
// GEMM geometry: CTA tile 128(m) x 128(n), stage = 32 k-elements (16 pairs),
// double-buffered. SA [2][128][20w] pair-packed; SB [2][32][68w] element rows
// (136 bf16, 128 used). 75776 B smem -> 2 CTAs/SM. 8 warps as 4(m) x 2(n);
// warp tile 32x64. 96 MMAs + 24 LDSM per warp per stage.
// ---------------------------------------------------------------------------
#define SA_BUF 2560                  // 128*20 words
#define SB_BUF 2176                  // 32*68 words
#define SB_STRIDE_E 136              // bf16 elements per SB row
#define G_SMEM_WORDS (2 * SA_BUF * 2 + 2 * SB_BUF * 2)   // 18944 words = 75776 B

#define GEMM_COMPUTE(sa_h, sa_l, sb_h, sb_l)                                       \
    _Pragma("unroll")                                                              \
    for (int kk = 0; kk < 2; kk++) {                                               \
        unsigned ah[2][4], al[2][4];                                               \
        _Pragma("unroll")                                                          \
        for (int mi = 0; mi < 2; mi++) {                                           \
            int mr = wm * 32 + mi * 16 + (lane & 15);                              \
            int kc = kk * 8 + ((lane >> 4) << 2);                                  \
            ldsm_x4(ah[mi], sa_h + mr * 20 + kc);                                  \
            ldsm_x4(al[mi], sa_l + mr * 20 + kc);                                  \
        }                                                                          \
        _Pragma("unroll")                                                          \
        for (int np = 0; np < 4; np++) {                                           \
            unsigned bh[4], bl[4];                                                 \
            int kr = kk * 16 + (lane & 15);                                        \
            int ne = wn * 64 + np * 16 + ((lane >> 4) << 3);                       \
            ldsm_x4_t(bh, (const ushort_t*)sb_h + kr * SB_STRIDE_E + ne);          \
            ldsm_x4_t(bl, (const ushort_t*)sb_l + kr * SB_STRIDE_E + ne);          \
            _Pragma("unroll")                                                      \
            for (int n2 = 0; n2 < 2; n2++) {                                       \
                _Pragma("unroll")                                                  \
                for (int mi = 0; mi < 2; mi++) {                                   \
                    mma_bf16(acc[mi][np * 2 + n2], ah[mi], &bh[n2 * 2]);           \
                    mma_bf16(acc[mi][np * 2 + n2], ah[mi], &bl[n2 * 2]);           \
                    mma_bf16(acc[mi][np * 2 + n2], al[mi], &bh[n2 * 2]);           \
                }                                                                  \
            }                                                                      \
        }                                                                          \
    }

// ---------------------------------------------------------------------------
// gemm1: H = relu(X @ W1 + b1) -> pair-packed g_Hp. grid (2, 157, 2)
// ---------------------------------------------------------------------------
__global__ __launch_bounds__(256, 2)
void gemm1(const float* __restrict__ b1s, const float* __restrict__ b1o)
{
    extern __shared__ unsigned sm[];
    unsigned* SA_hi = sm;
    unsigned* SA_lo = SA_hi + 2 * SA_BUF;
    unsigned* SB_hi = SA_lo + 2 * SA_BUF;
    unsigned* SB_lo = SB_hi + 2 * SB_BUF;

    const int tid = threadIdx.x, warp = tid >> 5, lane = tid & 31;
    const int g = lane >> 2, t = lane & 3;
    const int wm = warp >> 1, wn = warp & 1;
    const int n0 = blockIdx.x * 128;
    const int row0 = blockIdx.y * 128;
    const int net = blockIdx.z;

    const ushort_t* __restrict__ Wh = g_W1e_hi[net];
    const ushort_t* __restrict__ Wl = g_W1e_lo[net];
    const float* __restrict__ b1 = net ? b1o : b1s;
    unsigned* __restrict__ Hh = g_Hp_hi[net];
    unsigned* __restrict__ Hl = g_Hp_lo[net];

    const int lrow = tid >> 2, lcol = (tid & 3) * 4;
    int ga0 = row0 + lrow;      if (ga0 >= N_DET) ga0 = N_DET - 1;
    int ga1 = row0 + lrow + 64; if (ga1 >= N_DET) ga1 = N_DET - 1;
    const int brow = tid >> 3, bchunk = (tid & 7) * 8;   // SB: 32 rows, 2x 8-elem chunks

#define LOAD1(s, buf) do {                                                        \
        size_t o0 = (size_t)ga0 * IN_P + (s) * 16 + lcol;                         \
        size_t o1 = (size_t)ga1 * IN_P + (s) * 16 + lcol;                         \
        unsigned* dh = SA_hi + (buf) * SA_BUF;                                    \
        unsigned* dl = SA_lo + (buf) * SA_BUF;                                    \
        cp16(&dh[lrow * 20 + lcol], &g_Xp_hi[o0]);                                \
        cp16(&dh[(lrow + 64) * 20 + lcol], &g_Xp_hi[o1]);                         \
        cp16(&dl[lrow * 20 + lcol], &g_Xp_lo[o0]);                                \
        cp16(&dl[(lrow + 64) * 20 + lcol], &g_Xp_lo[o1]);                         \
        size_t ob = (size_t)((s) * 32 + brow) * HID_DIM + n0 + bchunk;            \
        ushort_t* sh = (ushort_t*)(SB_hi + (buf) * SB_BUF) + brow * SB_STRIDE_E;  \
        ushort_t* sl = (ushort_t*)(SB_lo + (buf) * SB_BUF) + brow * SB_STRIDE_E;  \
        cp16(sh + bchunk,      &Wh[ob]);                                          \
        cp16(sh + bchunk + 64, &Wh[ob + 64]);                                     \
        cp16(sl + bchunk,      &Wl[ob]);                                          \
        cp16(sl + bchunk + 64, &Wl[ob + 64]);                                     \
        asm volatile("cp.async.commit_group;" ::: "memory");                      \
    } while (0)

    float acc[2][8][4];
#pragma unroll
    for (int mi = 0; mi < 2; mi++)
#pragma unroll
        for (int ni = 0; ni < 8; ni++)
#pragma unroll
            for (int r = 0; r < 4; r++) acc[mi][ni][r] = 0.f;

    LOAD1(0, 0);
    for (int s = 0; s < 5; s++) {
        if (s < 4) {
            LOAD1(s + 1, (s + 1) & 1);
            asm volatile("cp.async.wait_group 1;" ::: "memory");
        } else {
            asm volatile("cp.async.wait_group 0;" ::: "memory");
        }
        __syncthreads();
        const unsigned* sa_h = SA_hi + (s & 1) * SA_BUF;
        const unsigned* sa_l = SA_lo + (s & 1) * SA_BUF;
        const unsigned* sb_h = SB_hi + (s & 1) * SB_BUF;
        const unsigned* sb_l = SB_lo + (s & 1) * SB_BUF;
        GEMM_COMPUTE(sa_h, sa_l, sb_h, sb_l)
        __syncthreads();
    }
#undef LOAD1

    // Epilogue: bias + relu, split-pack, write H pairs
#pragma unroll
    for (int mi = 0; mi < 2; mi++) {
        int r0 = row0 + wm * 32 + mi * 16 + g;
        int r1 = r0 + 8;
#pragma unroll
        for (int ni = 0; ni < 8; ni++) {
            int c0 = n0 + wn * 64 + ni * 8 + 2 * t;
            float bb0 = __ldg(&b1[c0]), bb1 = __ldg(&b1[c0 + 1]);
            float v00 = fmaxf(acc[mi][ni][0] + bb0, 0.f);
            float v01 = fmaxf(acc[mi][ni][1] + bb1, 0.f);
            float v10 = fmaxf(acc[mi][ni][2] + bb0, 0.f);
            float v11 = fmaxf(acc[mi][ni][3] + bb1, 0.f);
            int k2 = c0 >> 1;
            unsigned hi, lo;
            if (r0 < N_DET) {
                split_pair(v00, v01, hi, lo);
                Hh[(size_t)r0 * HID_P + k2] = hi;
                Hl[(size_t)r0 * HID_P + k2] = lo;
            }
            if (r1 < N_DET) {
                split_pair(v10, v11, hi, lo);
                Hh[(size_t)r1 * HID_P + k2] = hi;
                Hl[(size_t)r1 * HID_P + k2] = lo;
            }
        }
    }
}

// ---------------------------------------------------------------------------
// gemm2: T = H @ W2 + b2 -> g_S / g_O.  grid (157, 2); full 128-n per CTA.
// ---------------------------------------------------------------------------
__global__ __launch_bounds__(256, 2)
void gemm2(const float* __restrict__ b2s, const float* __restrict__ b2o)
{
    extern __shared__ unsigned sm[];
    unsigned* SA_hi = sm;
    unsigned* SA_lo = SA_hi + 2 * SA_BUF;
    unsigned* SB_hi = SA_lo + 2 * SA_BUF;
    unsigned* SB_lo = SB_hi + 2 * SB_BUF;

    const int tid = threadIdx.x, warp = tid >> 5, lane = tid & 31;
    const int g = lane >> 2, t = lane & 3;
    const int wm = warp >> 1, wn = warp & 1;
    const int row0 = blockIdx.x * 128;
    const int net = blockIdx.y;

    const unsigned* __restrict__ Ah = g_Hp_hi[net];
    const unsigned* __restrict__ Al = g_Hp_lo[net];
    const ushort_t* __restrict__ Wh = g_W2e_hi[net];
    const ushort_t* __restrict__ Wl = g_W2e_lo[net];
    const float* __restrict__ b2 = net ? b2o : b2s;
    float* __restrict__ out = net ? g_O : g_S;

    const int lrow = tid >> 2, lcol = (tid & 3) * 4;
    int ga0 = row0 + lrow;      if (ga0 >= N_DET) ga0 = N_DET - 1;
    int ga1 = row0 + lrow + 64; if (ga1 >= N_DET) ga1 = N_DET - 1;
    const int brow = tid >> 3, bchunk = (tid & 7) * 8;

#define LOAD2(s, buf) do {                                                        \
        size_t o0 = (size_t)ga0 * HID_P + (s) * 16 + lcol;                        \
        size_t o1 = (size_t)ga1 * HID_P + (s) * 16 + lcol;                        \
        unsigned* dh = SA_hi + (buf) * SA_BUF;                                    \
        unsigned* dl = SA_lo + (buf) * SA_BUF;                                    \
        cp16(&dh[lrow * 20 + lcol], &Ah[o0]);                                     \
        cp16(&dh[(lrow + 64) * 20 + lcol], &Ah[o1]);                              \
        cp16(&dl[lrow * 20 + lcol], &Al[o0]);                                     \
        cp16(&dl[(lrow + 64) * 20 + lcol], &Al[o1]);                              \
        size_t ob = (size_t)((s) * 32 + brow) * OUT_DIM + bchunk;                 \
        ushort_t* sh = (ushort_t*)(SB_hi + (buf) * SB_BUF) + brow * SB_STRIDE_E;  \
        ushort_t* sl = (ushort_t*)(SB_lo + (buf) * SB_BUF) + brow * SB_STRIDE_E;  \
        cp16(sh + bchunk,      &Wh[ob]);                                          \
        cp16(sh + bchunk + 64, &Wh[ob + 64]);                                     \
        cp16(sl + bchunk,      &Wl[ob]);                                          \
        cp16(sl + bchunk + 64, &Wl[ob + 64]);                                     \
        asm volatile("cp.async.commit_group;" ::: "memory");                      \
    } while (0)

    float acc[2][8][4];
#pragma unroll
    for (int mi = 0; mi < 2; mi++)
#pragma unroll
        for (int ni = 0; ni < 8; ni++)
#pragma unroll
            for (int r = 0; r < 4; r++) acc[mi][ni][r] = 0.f;

    LOAD2(0, 0);
    for (int s = 0; s < 8; s++) {
        if (s < 7) {
            LOAD2(s + 1, (s + 1) & 1);
            asm volatile("cp.async.wait_group 1;" ::: "memory");
        } else {
            asm volatile("cp.async.wait_group 0;" ::: "memory");
        }
        __syncthreads();
        const unsigned* sa_h = SA_hi + (s & 1) * SA_BUF;
        const unsigned* sa_l = SA_lo + (s & 1) * SA_BUF;
        const unsigned* sb_h = SB_hi + (s & 1) * SB_BUF;
        const unsigned* sb_l = SB_lo + (s & 1) * SB_BUF;
        GEMM_COMPUTE(sa_h, sa_l, sb_h, sb_l)
        __syncthreads();
    }
#undef LOAD2

    // Output epilogue
#pragma unroll
    for (int mi = 0; mi < 2; mi++) {
        int r0 = row0 + wm * 32 + mi * 16 + g;
        int r1 = r0 + 8;
#pragma unroll
        for (int ni = 0; ni < 8; ni++) {
            int c = wn * 64 + ni * 8 + 2 * t;
            float bb0 = __ldg(&b2[c]), bb1 = __ldg(&b2[c + 1]);
            float2 v0 = make_float2(acc[mi][ni][0] + bb0, acc[mi][ni][1] + bb1);
            float2 v1 = make_float2(acc[mi][ni][2] + bb0, acc[mi][ni][3] + bb1);
            if (r0 < N_DET) *reinterpret_cast<float2*>(&out[(size_t)r0 * OUT_DIM + c]) = v0;
            if (r1 < N_DET) *reinterpret_cast<float2*>(&out[(size_t)r1 * OUT_DIM + c]) = v1;
        }
    }
}

// ---------------------------------------------------------------------------
// Edge phase: 8 lanes per edge (4 edges per warp).
// ---------------------------------------------------------------------------
__global__ void __launch_bounds__(256)
edge_kernel(const void* __restrict__ einds, float* __restrict__ out, int nE)
{
    long long warp = (long long)((blockIdx.x * blockDim.x + threadIdx.x) >> 5);
    int lane = threadIdx.x & 31;
    int sub = lane >> 3;
    int l   = lane & 7;
    long long e = warp * 4 + sub;
    if (e >= nE) return;

    long long i1, i2;
    if (g_idx64) {
        const long long* E = (const long long*)einds;
        i1 = __ldg(&E[3 * e + 1]);
        i2 = __ldg(&E[3 * e + 2]);
    } else {
        const int* E = (const int*)einds;
        i1 = __ldg(&E[3 * e + 1]);
        i2 = __ldg(&E[3 * e + 2]);
    }

    const float4* s = reinterpret_cast<const float4*>(g_S + i1 * OUT_DIM);
    const float4* o = reinterpret_cast<const float4*>(g_O + i2 * OUT_DIM);

    float4 a0 = s[l], a1 = s[l + 8], a2 = s[l + 16], a3 = s[l + 24];
    float4 b0 = o[l], b1 = o[l + 8], b2 = o[l + 16], b3 = o[l + 24];

    float sum = a0.x * b0.x + a0.y * b0.y + a0.z * b0.z + a0.w * b0.w
              + a1.x * b1.x + a1.y * b1.y + a1.z * b1.z + a1.w * b1.w
              + a2.x * b2.x + a2.y * b2.y + a2.z * b2.z + a2.w * b2.w
              + a3.x * b3.x + a3.y * b3.y + a3.z * b3.z + a3.w * b3.w;

    sum += __shfl_xor_sync(0xffffffffu, sum, 4);
    sum += __shfl_xor_sync(0xffffffffu, sum, 2);
    sum += __shfl_xor_sync(0xffffffffu, sum, 1);

    if (l == 0)
        out[e] = 1.f / (1.f + __expf(-sum));
}

extern "C" void kernel_launch(void* const* d_in, const int* in_sizes, int n_in,
                              void* d_out, int out_size)
{
    const float* X     = (const float*)d_in[0];
    const void*  E     = d_in[1];
    const float* Ws_w1 = (const float*)d_in[2];
    const float* Ws_b1 = (const float*)d_in[3];
    const float* Ws_w2 = (const float*)d_in[4];
    const float* Ws_b2 = (const float*)d_in[5];
    const float* Wo_w1 = (const float*)d_in[6];
    const float* Wo_b1 = (const float*)d_in[7];
    const float* Wo_w2 = (const float*)d_in[8];
    const float* Wo_b2 = (const float*)d_in[9];

    cudaFuncSetAttribute(gemm1, cudaFuncAttributeMaxDynamicSharedMemorySize,
                         G_SMEM_WORDS * 4);
    cudaFuncSetAttribute(gemm2, cudaFuncAttributeMaxDynamicSharedMemorySize,
                         G_SMEM_WORDS * 4);

    probe_dtype<<<1, 1>>>((const long long*)E);

    int nx = N_DET * IN_P;
    prep_X<<<(nx + 255) / 256, 256>>>(X);
    int nw = 2 * IN_E * HID_DIM + 2 * HID_DIM * OUT_DIM;
    prep_W<<<(nw + 255) / 256, 256>>>(Ws_w1, Wo_w1, Ws_w2, Wo_w2);

    dim3 g1(HID_DIM / 128, (N_DET + 127) / 128, 2);  // (2, 157, 2)
    gemm1<<<g1, 256, G_SMEM_WORDS * 4>>>(Ws_b1, Wo_b1);

    dim3 g2((N_DET + 127) / 128, 2);                 // (157, 2)
    gemm2<<<g2, 256, G_SMEM_WORDS * 4>>>(Ws_b2, Wo_b2);

    int nE = in_sizes[1] / 3;                        // 1,000,000
    long long totalWarps = ((long long)nE + 3) / 4;
    long long totalThreads = totalWarps * 32;
    int nThreads = 256;
    int nBlocks = (int)((totalThreads + nThreads - 1) / nThreads);
    edge_kernel<<<nBlocks, nThreads>>>(E, (float*)d_out, nE);
}

// round 15
// speedup vs baseline: 1.1445x; 1.1445x over previous
#include <cuda_runtime.h>
#include <cuda_bf16.h>
#include <cuda_fp16.h>

// Problem constants
#define N_DET   20000
#define IN_DIM  151
#define HID_DIM 256
#define OUT_DIM 128
#define IN_P    80       // k-pairs for IN_DIM (76 real, 4 zero) -> 5 stages of 16
#define HID_P   128      // k-pairs for HID_DIM -> 8 stages of 16
#define IN_E    160      // padded elements

typedef unsigned short ushort_t;

// Scratch (allocation forbidden -> __device__ globals)
__device__ __align__(16) __half   g_S16[N_DET * OUT_DIM];      // fp16 subject table
__device__ __align__(16) __half   g_O16[N_DET * OUT_DIM];      // fp16 object table
__device__ __align__(16) unsigned g_Xp_hi[N_DET * IN_P];       // pair-packed rows
__device__ __align__(16) unsigned g_Xp_lo[N_DET * IN_P];
__device__ __align__(16) unsigned g_Hp_hi[2][N_DET * HID_P];   // pair-packed H
__device__ __align__(16) unsigned g_Hp_lo[2][N_DET * HID_P];
__device__ __align__(16) ushort_t g_W1e_hi[2][IN_E * HID_DIM]; // element [k][n]
__device__ __align__(16) ushort_t g_W1e_lo[2][IN_E * HID_DIM];
__device__ __align__(16) ushort_t g_W2e_hi[2][HID_DIM * OUT_DIM];
__device__ __align__(16) ushort_t g_W2e_lo[2][HID_DIM * OUT_DIM];
__device__ int g_idx64;

// ---------------------------------------------------------------------------
__global__ void probe_dtype(const long long* __restrict__ e)
{
    bool ok64 = true;
    for (int i = 0; i < 48; i++) {
        long long v = e[i];
        if (v < 0 || v >= N_DET) ok64 = false;
    }
    g_idx64 = ok64 ? 1 : 0;
}

// ---------------------------------------------------------------------------
// bf16 helpers
// ---------------------------------------------------------------------------
__device__ __forceinline__ void split_bf16(float v, ushort_t& hi, ushort_t& lo)
{
    __nv_bfloat16 h = __float2bfloat16(v);
    __nv_bfloat16 l = __float2bfloat16(v - __bfloat162float(h));
    hi = __bfloat16_as_ushort(h);
    lo = __bfloat16_as_ushort(l);
}
__device__ __forceinline__ unsigned pack2(ushort_t a, ushort_t b)
{
    return (unsigned)a | ((unsigned)b << 16);
}
__device__ __forceinline__ void split_pair(float v0, float v1, unsigned& hi, unsigned& lo)
{
    ushort_t h0, l0, h1, l1;
    split_bf16(v0, h0, l0);
    split_bf16(v1, h1, l1);
    hi = pack2(h0, h1);
    lo = pack2(l0, l1);
}

__device__ __forceinline__ void mma_bf16(float* d, const unsigned* a, const unsigned* b)
{
    asm("mma.sync.aligned.m16n8k16.row.col.f32.bf16.bf16.f32 "
        "{%0,%1,%2,%3}, {%4,%5,%6,%7}, {%8,%9}, {%0,%1,%2,%3};"
        : "+f"(d[0]), "+f"(d[1]), "+f"(d[2]), "+f"(d[3])
        : "r"(a[0]), "r"(a[1]), "r"(a[2]), "r"(a[3]), "r"(b[0]), "r"(b[1]));
}

__device__ __forceinline__ void ldsm_x4(unsigned* r, const void* p)
{
    unsigned a = (unsigned)__cvta_generic_to_shared(p);
    asm volatile("ldmatrix.sync.aligned.m8n8.x4.shared.b16 {%0,%1,%2,%3}, [%4];"
                 : "=r"(r[0]), "=r"(r[1]), "=r"(r[2]), "=r"(r[3]) : "r"(a));
}
__device__ __forceinline__ void ldsm_x4_t(unsigned* r, const void* p)
{
    unsigned a = (unsigned)__cvta_generic_to_shared(p);
    asm volatile("ldmatrix.sync.aligned.m8n8.x4.trans.shared.b16 {%0,%1,%2,%3}, [%4];"
                 : "=r"(r[0]), "=r"(r[1]), "=r"(r[2]), "=r"(r[3]) : "r"(a));
}

// cp.async 16B global->shared
__device__ __forceinline__ void cp16(const void* dst, const void* src)
{
    unsigned d = (unsigned)__cvta_generic_to_shared(dst);
    asm volatile("cp.async.cg.shared.global [%0], [%1], 16;" :: "r"(d), "l"(src));
}

// ---------------------------------------------------------------------------
// Prep kernels
// ---------------------------------------------------------------------------
__global__ void prep_X(const float* __restrict__ X)
{
    int idx = blockIdx.x * blockDim.x + threadIdx.x;
    if (idx >= N_DET * IN_P) return;
    int row = idx / IN_P, j = idx - row * IN_P;
    float v0 = (2 * j     < IN_DIM) ? X[(size_t)row * IN_DIM + 2 * j]     : 0.f;
    float v1 = (2 * j + 1 < IN_DIM) ? X[(size_t)row * IN_DIM + 2 * j + 1] : 0.f;
    unsigned hi, lo;
    split_pair(v0, v1, hi, lo);
    g_Xp_hi[idx] = hi;
    g_Xp_lo[idx] = lo;
}

__global__ void prep_W(const float* __restrict__ Ws_w1, const float* __restrict__ Wo_w1,
                       const float* __restrict__ Ws_w2, const float* __restrict__ Wo_w2)
{
    int idx = blockIdx.x * blockDim.x + threadIdx.x;
    const int W1TOT = 2 * IN_E * HID_DIM;     // 81920
    const int W2TOT = 2 * HID_DIM * OUT_DIM;  // 65536
    if (idx < W1TOT) {
        int net = idx / (IN_E * HID_DIM);
        int r = idx - net * (IN_E * HID_DIM);
        int k = r / HID_DIM, n = r - k * HID_DIM;
        const float* W = net ? Wo_w1 : Ws_w1;
        float v = (k < IN_DIM) ? W[(size_t)k * HID_DIM + n] : 0.f;
        ushort_t hi, lo;
        split_bf16(v, hi, lo);
        g_W1e_hi[net][r] = hi;
        g_W1e_lo[net][r] = lo;
    } else if (idx < W1TOT + W2TOT) {
        int j = idx - W1TOT;
        int net = j / (HID_DIM * OUT_DIM);
        int r = j - net * (HID_DIM * OUT_DIM);
        float v = (net ? Wo_w2 : Ws_w2)[r];
        ushort_t hi, lo;
        split_bf16(v, hi, lo);
        g_W2e_hi[net][r] = hi;
        g_W2e_lo[net][r] = lo;
    }
}

// ---------------------------------------------------------------------------
// GEMM geometry (R12-proven): CTA tile 128(m) x 64(n), stage = 32 k-elements,
// double-buffered. SA [2][128][20w] pair-packed; SB [2][32][36w] element rows.
// 59392 B smem -> 3 CTAs/SM. 8 warps as 4(m) x 2(n); warp tile 32x32.
// ---------------------------------------------------------------------------
#define SA_BUF 2560                  // 128*20 words
#define SB_BUF 1152                  // 32*36 words
#define G_SMEM_WORDS (2 * SA_BUF * 2 + 2 * SB_BUF * 2)   // 14848 words = 59392 B

#define GEMM_COMPUTE(sa_h, sa_l, sb_h, sb_l)                                       \
    _Pragma("unroll")                                                              \
    for (int kk = 0; kk < 2; kk++) {                                               \
        unsigned ah[2][4], al[2][4];                                               \
        _Pragma("unroll")                                                          \
        for (int mi = 0; mi < 2; mi++) {                                           \
            int mr = wm * 32 + mi * 16 + (lane & 15);                              \
            int kc = kk * 8 + ((lane >> 4) << 2);                                  \
            ldsm_x4(ah[mi], sa_h + mr * 20 + kc);                                  \
            ldsm_x4(al[mi], sa_l + mr * 20 + kc);                                  \
        }                                                                          \
        _Pragma("unroll")                                                          \
        for (int np = 0; np < 2; np++) {                                           \
            unsigned bh[4], bl[4];                                                 \
            int kr = kk * 16 + (lane & 15);                                        \
            int ne = wn * 32 + np * 16 + ((lane >> 4) << 3);                       \
            ldsm_x4_t(bh, (const ushort_t*)sb_h + kr * 72 + ne);                   \
            ldsm_x4_t(bl, (const ushort_t*)sb_l + kr * 72 + ne);                   \
            _Pragma("unroll")                                                      \
            for (int n2 = 0; n2 < 2; n2++) {                                       \
                _Pragma("unroll")                                                  \
                for (int mi = 0; mi < 2; mi++) {                                   \
                    mma_bf16(acc[mi][np * 2 + n2], ah[mi], &bh[n2 * 2]);           \
                    mma_bf16(acc[mi][np * 2 + n2], ah[mi], &bl[n2 * 2]);           \
                    mma_bf16(acc[mi][np * 2 + n2], al[mi], &bh[n2 * 2]);           \
                }                                                                  \
            }                                                                      \
        }                                                                          \
    }

// ---------------------------------------------------------------------------
// gemm1: H = relu(X @ W1 + b1) -> pair-packed g_Hp. grid (4, 157, 2)
// ---------------------------------------------------------------------------
__global__ __launch_bounds__(256, 3)
void gemm1(const float* __restrict__ b1s, const float* __restrict__ b1o)
{
    extern __shared__ unsigned sm[];
    unsigned* SA_hi = sm;
    unsigned* SA_lo = SA_hi + 2 * SA_BUF;
    unsigned* SB_hi = SA_lo + 2 * SA_BUF;
    unsigned* SB_lo = SB_hi + 2 * SB_BUF;

    const int tid = threadIdx.x, warp = tid >> 5, lane = tid & 31;
    const int g = lane >> 2, t = lane & 3;
    const int wm = warp >> 1, wn = warp & 1;
    const int n0 = blockIdx.x * 64;
    const int row0 = blockIdx.y * 128;
    const int net = blockIdx.z;

    const ushort_t* __restrict__ Wh = g_W1e_hi[net];
    const ushort_t* __restrict__ Wl = g_W1e_lo[net];
    const float* __restrict__ b1 = net ? b1o : b1s;
    unsigned* __restrict__ Hh = g_Hp_hi[net];
    unsigned* __restrict__ Hl = g_Hp_lo[net];

    const int lrow = tid >> 2, lcol = (tid & 3) * 4;
    int ga0 = row0 + lrow;      if (ga0 >= N_DET) ga0 = N_DET - 1;
    int ga1 = row0 + lrow + 64; if (ga1 >= N_DET) ga1 = N_DET - 1;
    const int brow = tid >> 3, bchunk = (tid & 7) * 8;   // SB: row 0..31, 8 elem chunk

#define LOAD1(s, buf) do {                                                        \
        size_t o0 = (size_t)ga0 * IN_P + (s) * 16 + lcol;                         \
        size_t o1 = (size_t)ga1 * IN_P + (s) * 16 + lcol;                         \
        unsigned* dh = SA_hi + (buf) * SA_BUF;                                    \
        unsigned* dl = SA_lo + (buf) * SA_BUF;                                    \
        cp16(&dh[lrow * 20 + lcol], &g_Xp_hi[o0]);                                \
        cp16(&dh[(lrow + 64) * 20 + lcol], &g_Xp_hi[o1]);                         \
        cp16(&dl[lrow * 20 + lcol], &g_Xp_lo[o0]);                                \
        cp16(&dl[(lrow + 64) * 20 + lcol], &g_Xp_lo[o1]);                         \
        size_t ob = (size_t)((s) * 32 + brow) * HID_DIM + n0 + bchunk;            \
        cp16((ushort_t*)(SB_hi + (buf) * SB_BUF) + brow * 72 + bchunk, &Wh[ob]);  \
        cp16((ushort_t*)(SB_lo + (buf) * SB_BUF) + brow * 72 + bchunk, &Wl[ob]);  \
        asm volatile("cp.async.commit_group;" ::: "memory");                      \
    } while (0)

    float acc[2][4][4];
#pragma unroll
    for (int mi = 0; mi < 2; mi++)
#pragma unroll
        for (int ni = 0; ni < 4; ni++)
#pragma unroll
            for (int r = 0; r < 4; r++) acc[mi][ni][r] = 0.f;

    LOAD1(0, 0);
    for (int s = 0; s < 5; s++) {
        if (s < 4) {
            LOAD1(s + 1, (s + 1) & 1);
            asm volatile("cp.async.wait_group 1;" ::: "memory");
        } else {
            asm volatile("cp.async.wait_group 0;" ::: "memory");
        }
        __syncthreads();
        const unsigned* sa_h = SA_hi + (s & 1) * SA_BUF;
        const unsigned* sa_l = SA_lo + (s & 1) * SA_BUF;
        const unsigned* sb_h = SB_hi + (s & 1) * SB_BUF;
        const unsigned* sb_l = SB_lo + (s & 1) * SB_BUF;
        GEMM_COMPUTE(sa_h, sa_l, sb_h, sb_l)
        __syncthreads();
    }
#undef LOAD1

    // Epilogue: bias + relu, split-pack, write H pairs
#pragma unroll
    for (int mi = 0; mi < 2; mi++) {
        int r0 = row0 + wm * 32 + mi * 16 + g;
        int r1 = r0 + 8;
#pragma unroll
        for (int ni = 0; ni < 4; ni++) {
            int c0 = n0 + wn * 32 + ni * 8 + 2 * t;
            float bb0 = __ldg(&b1[c0]), bb1 = __ldg(&b1[c0 + 1]);
            float v00 = fmaxf(acc[mi][ni][0] + bb0, 0.f);
            float v01 = fmaxf(acc[mi][ni][1] + bb1, 0.f);
            float v10 = fmaxf(acc[mi][ni][2] + bb0, 0.f);
            float v11 = fmaxf(acc[mi][ni][3] + bb1, 0.f);
            int k2 = c0 >> 1;
            unsigned hi, lo;
            if (r0 < N_DET) {
                split_pair(v00, v01, hi, lo);
                Hh[(size_t)r0 * HID_P + k2] = hi;
                Hl[(size_t)r0 * HID_P + k2] = lo;
            }
            if (r1 < N_DET) {
                split_pair(v10, v11, hi, lo);
                Hh[(size_t)r1 * HID_P + k2] = hi;
                Hl[(size_t)r1 * HID_P + k2] = lo;
            }
        }
    }
}

// ---------------------------------------------------------------------------
// gemm2: T = H @ W2 + b2 -> fp16 tables g_S16 / g_O16.  grid (2, 157, 2)
// ---------------------------------------------------------------------------
__global__ __launch_bounds__(256, 3)
void gemm2(const float* __restrict__ b2s, const float* __restrict__ b2o)
{
    extern __shared__ unsigned sm[];
    unsigned* SA_hi = sm;
    unsigned* SA_lo = SA_hi + 2 * SA_BUF;
    unsigned* SB_hi = SA_lo + 2 * SA_BUF;
    unsigned* SB_lo = SB_hi + 2 * SB_BUF;

    const int tid = threadIdx.x, warp = tid >> 5, lane = tid & 31;
    const int g = lane >> 2, t = lane & 3;
    const int wm = warp >> 1, wn = warp & 1;
    const int n0 = blockIdx.x * 64;
    const int row0 = blockIdx.y * 128;
    const int net = blockIdx.z;

    const unsigned* __restrict__ Ah = g_Hp_hi[net];
    const unsigned* __restrict__ Al = g_Hp_lo[net];
    const ushort_t* __restrict__ Wh = g_W2e_hi[net];
    const ushort_t* __restrict__ Wl = g_W2e_lo[net];
    const float* __restrict__ b2 = net ? b2o : b2s;
    __half* __restrict__ out = net ? g_O16 : g_S16;

    const int lrow = tid >> 2, lcol = (tid & 3) * 4;
    int ga0 = row0 + lrow;      if (ga0 >= N_DET) ga0 = N_DET - 1;
    int ga1 = row0 + lrow + 64; if (ga1 >= N_DET) ga1 = N_DET - 1;
    const int brow = tid >> 3, bchunk = (tid & 7) * 8;

#define LOAD2(s, buf) do {                                                        \
        size_t o0 = (size_t)ga0 * HID_P + (s) * 16 + lcol;                        \
        size_t o1 = (size_t)ga1 * HID_P + (s) * 16 + lcol;                        \
        unsigned* dh = SA_hi + (buf) * SA_BUF;                                    \
        unsigned* dl = SA_lo + (buf) * SA_BUF;                                    \
        cp16(&dh[lrow * 20 + lcol], &Ah[o0]);                                     \
        cp16(&dh[(lrow + 64) * 20 + lcol], &Ah[o1]);                              \
        cp16(&dl[lrow * 20 + lcol], &Al[o0]);                                     \
        cp16(&dl[(lrow + 64) * 20 + lcol], &Al[o1]);                              \
        size_t ob = (size_t)((s) * 32 + brow) * OUT_DIM + n0 + bchunk;            \
        cp16((ushort_t*)(SB_hi + (buf) * SB_BUF) + brow * 72 + bchunk, &Wh[ob]);  \
        cp16((ushort_t*)(SB_lo + (buf) * SB_BUF) + brow * 72 + bchunk, &Wl[ob]);  \
        asm volatile("cp.async.commit_group;" ::: "memory");                      \
    } while (0)

    float acc[2][4][4];
#pragma unroll
    for (int mi = 0; mi < 2; mi++)
#pragma unroll
        for (int ni = 0; ni < 4; ni++)
#pragma unroll
            for (int r = 0; r < 4; r++) acc[mi][ni][r] = 0.f;

    LOAD2(0, 0);
    for (int s = 0; s < 8; s++) {
        if (s < 7) {
            LOAD2(s + 1, (s + 1) & 1);
            asm volatile("cp.async.wait_group 1;" ::: "memory");
        } else {
            asm volatile("cp.async.wait_group 0;" ::: "memory");
        }
        __syncthreads();
        const unsigned* sa_h = SA_hi + (s & 1) * SA_BUF;
        const unsigned* sa_l = SA_lo + (s & 1) * SA_BUF;
        const unsigned* sb_h = SB_hi + (s & 1) * SB_BUF;
        const unsigned* sb_l = SB_lo + (s & 1) * SB_BUF;
        GEMM_COMPUTE(sa_h, sa_l, sb_h, sb_l)
        __syncthreads();
    }
#undef LOAD2

    // Output epilogue: fp16 table stores (half2 per register pair)
#pragma unroll
    for (int mi = 0; mi < 2; mi++) {
        int r0 = row0 + wm * 32 + mi * 16 + g;
        int r1 = r0 + 8;
#pragma unroll
        for (int ni = 0; ni < 4; ni++) {
            int c = n0 + wn * 32 + ni * 8 + 2 * t;
            float bb0 = __ldg(&b2[c]), bb1 = __ldg(&b2[c + 1]);
            if (r0 < N_DET)
                *reinterpret_cast<__half2*>(&out[(size_t)r0 * OUT_DIM + c]) =
                    __floats2half2_rn(acc[mi][ni][0] + bb0, acc[mi][ni][1] + bb1);
            if (r1 < N_DET)
                *reinterpret_cast<__half2*>(&out[(size_t)r1 * OUT_DIM + c]) =
                    __floats2half2_rn(acc[mi][ni][2] + bb0, acc[mi][ni][3] + bb1);
        }
    }
}

// ---------------------------------------------------------------------------
// Edge phase: 8 lanes per edge (4 edges per warp), fp16 tables.
// Per lane: 2x 16B of sbj + 2x 16B of obj (16 halfs each side).
// ---------------------------------------------------------------------------
__device__ __forceinline__ float dot2h(unsigned a, unsigned b)
{
    float2 fa = __half22float2(*reinterpret_cast<__half2*>(&a));
    float2 fb = __half22float2(*reinterpret_cast<__half2*>(&b));
    return fa.x * fb.x + fa.y * fb.y;
}

__global__ void __launch_bounds__(256)
edge_kernel(const void* __restrict__ einds, float* __restrict__ out, int nE)
{
    long long warp = (long long)((blockIdx.x * blockDim.x + threadIdx.x) >> 5);
    int lane = threadIdx.x & 31;
    int sub = lane >> 3;
    int l   = lane & 7;
    long long e = warp * 4 + sub;
    if (e >= nE) return;

    long long i1, i2;
    if (g_idx64) {
        const long long* E = (const long long*)einds;
        i1 = __ldg(&E[3 * e + 1]);
        i2 = __ldg(&E[3 * e + 2]);
    } else {
        const int* E = (const int*)einds;
        i1 = __ldg(&E[3 * e + 1]);
        i2 = __ldg(&E[3 * e + 2]);
    }

    const uint4* s = reinterpret_cast<const uint4*>(g_S16 + i1 * OUT_DIM);
    const uint4* o = reinterpret_cast<const uint4*>(g_O16 + i2 * OUT_DIM);

    uint4 a0 = s[l], a1 = s[l + 8];
    uint4 b0 = o[l], b1 = o[l + 8];

    float sum = dot2h(a0.x, b0.x) + dot2h(a0.y, b0.y)
              + dot2h(a0.z, b0.z) + dot2h(a0.w, b0.w)
              + dot2h(a1.x, b1.x) + dot2h(a1.y, b1.y)
              + dot2h(a1.z, b1.z) + dot2h(a1.w, b1.w);

    sum += __shfl_xor_sync(0xffffffffu, sum, 4);
    sum += __shfl_xor_sync(0xffffffffu, sum, 2);
    sum += __shfl_xor_sync(0xffffffffu, sum, 1);

    if (l == 0)
        out[e] = 1.f / (1.f + __expf(-sum));
}

extern "C" void kernel_launch(void* const* d_in, const int* in_sizes, int n_in,
                              void* d_out, int out_size)
{
    const float* X     = (const float*)d_in[0];
    const void*  E     = d_in[1];
    const float* Ws_w1 = (const float*)d_in[2];
    const float* Ws_b1 = (const float*)d_in[3];
    const float* Ws_w2 = (const float*)d_in[4];
    const float* Ws_b2 = (const float*)d_in[5];
    const float* Wo_w1 = (const float*)d_in[6];
    const float* Wo_b1 = (const float*)d_in[7];
    const float* Wo_w2 = (const float*)d_in[8];
    const float* Wo_b2 = (const float*)d_in[9];

    cudaFuncSetAttribute(gemm1, cudaFuncAttributeMaxDynamicSharedMemorySize,
                         G_SMEM_WORDS * 4);
    cudaFuncSetAttribute(gemm2, cudaFuncAttributeMaxDynamicSharedMemorySize,
                         G_SMEM_WORDS * 4);

    probe_dtype<<<1, 1>>>((const long long*)E);

    int nx = N_DET * IN_P;
    prep_X<<<(nx + 255) / 256, 256>>>(X);
    int nw = 2 * IN_E * HID_DIM + 2 * HID_DIM * OUT_DIM;
    prep_W<<<(nw + 255) / 256, 256>>>(Ws_w1, Wo_w1, Ws_w2, Wo_w2);

    dim3 g1(HID_DIM / 64, (N_DET + 127) / 128, 2);   // (4, 157, 2)
    gemm1<<<g1, 256, G_SMEM_WORDS * 4>>>(Ws_b1, Wo_b1);

    dim3 g2(OUT_DIM / 64, (N_DET + 127) / 128, 2);   // (2, 157, 2)
    gemm2<<<g2, 256, G_SMEM_WORDS * 4>>>(Ws_b2, Wo_b2);

    int nE = in_sizes[1] / 3;                        // 1,000,000
    long long totalWarps = ((long long)nE + 3) / 4;
    long long totalThreads = totalWarps * 32;
    int nThreads = 256;
    int nBlocks = (int)((totalThreads + nThreads - 1) / nThreads);
    edge_kernel<<<nBlocks, nThreads>>>(E, (float*)d_out, nE);
}

// round 17
// speedup vs baseline: 1.1595x; 1.0131x over previous
#include <cuda_runtime.h>
#include <cuda_bf16.h>
#include <cuda_fp16.h>

// Problem constants
#define N_DET   20000
#define IN_DIM  151
#define HID_DIM 256
#define OUT_DIM 128
#define IN_P    80       // k-pairs for IN_DIM (76 real, 4 zero) -> 5 stages of 16
#define HID_P   128      // k-pairs for HID_DIM -> 8 stages of 16
#define IN_E    160      // padded elements

typedef unsigned short ushort_t;

// Scratch (allocation forbidden -> __device__ globals)
__device__ __align__(16) __half   g_S16[N_DET * OUT_DIM];      // fp16 subject table
__device__ __align__(16) __half   g_O16[N_DET * OUT_DIM];      // fp16 object table
__device__ __align__(16) unsigned g_Xp_hi[N_DET * IN_P];       // pair-packed rows
__device__ __align__(16) unsigned g_Xp_lo[N_DET * IN_P];
__device__ __align__(16) unsigned g_Hp_hi[2][N_DET * HID_P];   // pair-packed H
__device__ __align__(16) unsigned g_Hp_lo[2][N_DET * HID_P];
__device__ __align__(16) ushort_t g_W1e_hi[2][IN_E * HID_DIM]; // element [k][n]
__device__ __align__(16) ushort_t g_W1e_lo[2][IN_E * HID_DIM];
__device__ __align__(16) ushort_t g_W2e_hi[2][HID_DIM * OUT_DIM];
__device__ __align__(16) ushort_t g_W2e_lo[2][HID_DIM * OUT_DIM];
__device__ int g_idx64;

// ---------------------------------------------------------------------------
__global__ void probe_dtype(const long long* __restrict__ e)
{
    bool ok64 = true;
    for (int i = 0; i < 48; i++) {
        long long v = e[i];
        if (v < 0 || v >= N_DET) ok64 = false;
    }
    g_idx64 = ok64 ? 1 : 0;
}

// ---------------------------------------------------------------------------
// bf16 helpers
// ---------------------------------------------------------------------------
__device__ __forceinline__ void split_bf16(float v, ushort_t& hi, ushort_t& lo)
{
    __nv_bfloat16 h = __float2bfloat16(v);
    __nv_bfloat16 l = __float2bfloat16(v - __bfloat162float(h));
    hi = __bfloat16_as_ushort(h);
    lo = __bfloat16_as_ushort(l);
}
__device__ __forceinline__ unsigned pack2(ushort_t a, ushort_t b)
{
    return (unsigned)a | ((unsigned)b << 16);
}
__device__ __forceinline__ void split_pair(float v0, float v1, unsigned& hi, unsigned& lo)
{
    ushort_t h0, l0, h1, l1;
    split_bf16(v0, h0, l0);
    split_bf16(v1, h1, l1);
    hi = pack2(h0, h1);
    lo = pack2(l0, l1);
}

__device__ __forceinline__ void mma_bf16(float* d, const unsigned* a, const unsigned* b)
{
    asm("mma.sync.aligned.m16n8k16.row.col.f32.bf16.bf16.f32 "
        "{%0,%1,%2,%3}, {%4,%5,%6,%7}, {%8,%9}, {%0,%1,%2,%3};"
        : "+f"(d[0]), "+f"(d[1]), "+f"(d[2]), "+f"(d[3])
        : "r"(a[0]), "r"(a[1]), "r"(a[2]), "r"(a[3]), "r"(b[0]), "r"(b[1]));
}

__device__ __forceinline__ void ldsm_x4(unsigned* r, const void* p)
{
    unsigned a = (unsigned)__cvta_generic_to_shared(p);
    asm volatile("ldmatrix.sync.aligned.m8n8.x4.shared.b16 {%0,%1,%2,%3}, [%4];"
                 : "=r"(r[0]), "=r"(r[1]), "=r"(r[2]), "=r"(r[3]) : "r"(a));
}
__device__ __forceinline__ void ldsm_x4_t(unsigned* r, const void* p)
{
    unsigned a = (unsigned)__cvta_generic_to_shared(p);
    asm volatile("ldmatrix.sync.aligned.m8n8.x4.trans.shared.b16 {%0,%1,%2,%3}, [%4];"
                 : "=r"(r[0]), "=r"(r[1]), "=r"(r[2]), "=r"(r[3]) : "r"(a));
}

// cp.async 16B global->shared
__device__ __forceinline__ void cp16(const void* dst, const void* src)
{
    unsigned d = (unsigned)__cvta_generic_to_shared(dst);
    asm volatile("cp.async.cg.shared.global [%0], [%1], 16;" :: "r"(d), "l"(src));
}

// ---------------------------------------------------------------------------
// Merged prep kernel: X pair-packed split + W element-major splits.
// ---------------------------------------------------------------------------
#define PREP_XTOT (N_DET * IN_P)              // 1,600,000
#define PREP_W1TOT (2 * IN_E * HID_DIM)       // 81,920
#define PREP_W2TOT (2 * HID_DIM * OUT_DIM)    // 65,536

__global__ void prep_all(const float* __restrict__ X,
                         const float* __restrict__ Ws_w1, const float* __restrict__ Wo_w1,
                         const float* __restrict__ Ws_w2, const float* __restrict__ Wo_w2)
{
    int idx = blockIdx.x * blockDim.x + threadIdx.x;
    if (idx < PREP_XTOT) {
        int row = idx / IN_P, j = idx - row * IN_P;
        float v0 = (2 * j     < IN_DIM) ? X[(size_t)row * IN_DIM + 2 * j]     : 0.f;
        float v1 = (2 * j + 1 < IN_DIM) ? X[(size_t)row * IN_DIM + 2 * j + 1] : 0.f;
        unsigned hi, lo;
        split_pair(v0, v1, hi, lo);
        g_Xp_hi[idx] = hi;
        g_Xp_lo[idx] = lo;
    } else if (idx < PREP_XTOT + PREP_W1TOT) {
        int i = idx - PREP_XTOT;
        int net = i / (IN_E * HID_DIM);
        int r = i - net * (IN_E * HID_DIM);
        int k = r / HID_DIM, n = r - k * HID_DIM;
        const float* W = net ? Wo_w1 : Ws_w1;
        float v = (k < IN_DIM) ? W[(size_t)k * HID_DIM + n] : 0.f;
        ushort_t hi, lo;
        split_bf16(v, hi, lo);
        g_W1e_hi[net][r] = hi;
        g_W1e_lo[net][r] = lo;
    } else if (idx < PREP_XTOT + PREP_W1TOT + PREP_W2TOT) {
        int i = idx - PREP_XTOT - PREP_W1TOT;
        int net = i / (HID_DIM * OUT_DIM);
        int r = i - net * (HID_DIM * OUT_DIM);
        float v = (net ? Wo_w2 : Ws_w2)[r];
        ushort_t hi, lo;
        split_bf16(v, hi, lo);
        g_W2e_hi[net][r] = hi;
        g_W2e_lo[net][r] = lo;
    }
}

// ---------------------------------------------------------------------------
// GEMM geometry (R12/R15-proven): CTA tile 128(m) x 64(n), stage = 32
// k-elements, double-buffered. SA [2][128][20w] pair-packed; SB [2][32][36w]
// element rows. 59392 B smem -> 3 CTAs/SM. 8 warps as 4(m) x 2(n); warp tile
// 32x32. Term-major MMA order: same-acc dependency distance = 4.
// ---------------------------------------------------------------------------
#define SA_BUF 2560                  // 128*20 words
#define SB_BUF 1152                  // 32*36 words
#define G_SMEM_WORDS (2 * SA_BUF * 2 + 2 * SB_BUF * 2)   // 14848 words = 59392 B

#define GEMM_COMPUTE(sa_h, sa_l, sb_h, sb_l)                                       \
    _Pragma("unroll")                                                              \
    for (int kk = 0; kk < 2; kk++) {                                               \
        unsigned ah[2][4], al[2][4];                                               \
        _Pragma("unroll")                                                          \
        for (int mi = 0; mi < 2; mi++) {                                           \
            int mr = wm * 32 + mi * 16 + (lane & 15);                              \
            int kc = kk * 8 + ((lane >> 4) << 2);                                  \
            ldsm_x4(ah[mi], sa_h + mr * 20 + kc);                                  \
            ldsm_x4(al[mi], sa_l + mr * 20 + kc);                                  \
        }                                                                          \
        _Pragma("unroll")                                                          \
        for (int np = 0; np < 2; np++) {                                           \
            unsigned bh[4], bl[4];                                                 \
            int kr = kk * 16 + (lane & 15);                                        \
            int ne = wn * 32 + np * 16 + ((lane >> 4) << 3);                       \
            ldsm_x4_t(bh, (const ushort_t*)sb_h + kr * 72 + ne);                   \
            ldsm_x4_t(bl, (const ushort_t*)sb_l + kr * 72 + ne);                   \
            /* term-major: 4 independent accs between dependent MMAs */            \
            _Pragma("unroll")                                                      \
            for (int mi = 0; mi < 2; mi++)                                         \
                _Pragma("unroll")                                                  \
                for (int n2 = 0; n2 < 2; n2++)                                     \
                    mma_bf16(acc[mi][np * 2 + n2], ah[mi], &bh[n2 * 2]);           \
            _Pragma("unroll")                                                      \
            for (int mi = 0; mi < 2; mi++)                                         \
                _Pragma("unroll")                                                  \
                for (int n2 = 0; n2 < 2; n2++)                                     \
                    mma_bf16(acc[mi][np * 2 + n2], ah[mi], &bl[n2 * 2]);           \
            _Pragma("unroll")                                                      \
            for (int mi = 0; mi < 2; mi++)                                         \
                _Pragma("unroll")                                                  \
                for (int n2 = 0; n2 < 2; n2++)                                     \
                    mma_bf16(acc[mi][np * 2 + n2], al[mi], &bh[n2 * 2]);           \
        }                                                                          \
    }

// ---------------------------------------------------------------------------
// gemm1: H = relu(X @ W1 + b1) -> pair-packed g_Hp. grid (4, 157, 2)
// ---------------------------------------------------------------------------
__global__ __launch_bounds__(256, 3)
void gemm1(const float* __restrict__ b1s, const float* __restrict__ b1o)
{
    extern __shared__ unsigned sm[];
    unsigned* SA_hi = sm;
    unsigned* SA_lo = SA_hi + 2 * SA_BUF;
    unsigned* SB_hi = SA_lo + 2 * SA_BUF;
    unsigned* SB_lo = SB_hi + 2 * SB_BUF;

    const int tid = threadIdx.x, warp = tid >> 5, lane = tid & 31;
    const int g = lane >> 2, t = lane & 3;
    const int wm = warp >> 1, wn = warp & 1;
    const int n0 = blockIdx.x * 64;
    const int row0 = blockIdx.y * 128;
    const int net = blockIdx.z;

    const ushort_t* __restrict__ Wh = g_W1e_hi[net];
    const ushort_t* __restrict__ Wl = g_W1e_lo[net];
    const float* __restrict__ b1 = net ? b1o : b1s;
    unsigned* __restrict__ Hh = g_Hp_hi[net];
    unsigned* __restrict__ Hl = g_Hp_lo[net];

    const int lrow = tid >> 2, lcol = (tid & 3) * 4;
    int ga0 = row0 + lrow;      if (ga0 >= N_DET) ga0 = N_DET - 1;
    int ga1 = row0 + lrow + 64; if (ga1 >= N_DET) ga1 = N_DET - 1;
    const int brow = tid >> 3, bchunk = (tid & 7) * 8;   // SB: row 0..31, 8 elem chunk

#define LOAD1(s, buf) do {                                                        \
        size_t o0 = (size_t)ga0 * IN_P + (s) * 16 + lcol;                         \
        size_t o1 = (size_t)ga1 * IN_P + (s) * 16 + lcol;                         \
        unsigned* dh = SA_hi + (buf) * SA_BUF;                                    \
        unsigned* dl = SA_lo + (buf) * SA_BUF;                                    \
        cp16(&dh[lrow * 20 + lcol], &g_Xp_hi[o0]);                                \
        cp16(&dh[(lrow + 64) * 20 + lcol], &g_Xp_hi[o1]);                         \
        cp16(&dl[lrow * 20 + lcol], &g_Xp_lo[o0]);                                \
        cp16(&dl[(lrow + 64) * 20 + lcol], &g_Xp_lo[o1]);                         \
        size_t ob = (size_t)((s) * 32 + brow) * HID_DIM + n0 + bchunk;            \
        cp16((ushort_t*)(SB_hi + (buf) * SB_BUF) + brow * 72 + bchunk, &Wh[ob]);  \
        cp16((ushort_t*)(SB_lo + (buf) * SB_BUF) + brow * 72 + bchunk, &Wl[ob]);  \
        asm volatile("cp.async.commit_group;" ::: "memory");                      \
    } while (0)

    float acc[2][4][4];
#pragma unroll
    for (int mi = 0; mi < 2; mi++)
#pragma unroll
        for (int ni = 0; ni < 4; ni++)
#pragma unroll
            for (int r = 0; r < 4; r++) acc[mi][ni][r] = 0.f;

    LOAD1(0, 0);
    for (int s = 0; s < 5; s++) {
        if (s < 4) {
            LOAD1(s + 1, (s + 1) & 1);
            asm volatile("cp.async.wait_group 1;" ::: "memory");
        } else {
            asm volatile("cp.async.wait_group 0;" ::: "memory");
        }
        __syncthreads();
        const unsigned* sa_h = SA_hi + (s & 1) * SA_BUF;
        const unsigned* sa_l = SA_lo + (s & 1) * SA_BUF;
        const unsigned* sb_h = SB_hi + (s & 1) * SB_BUF;
        const unsigned* sb_l = SB_lo + (s & 1) * SB_BUF;
        GEMM_COMPUTE(sa_h, sa_l, sb_h, sb_l)
        __syncthreads();
    }
#undef LOAD1

    // Epilogue: bias + relu, split-pack, write H pairs
#pragma unroll
    for (int mi = 0; mi < 2; mi++) {
        int r0 = row0 + wm * 32 + mi * 16 + g;
        int r1 = r0 + 8;
#pragma unroll
        for (int ni = 0; ni < 4; ni++) {
            int c0 = n0 + wn * 32 + ni * 8 + 2 * t;
            float bb0 = __ldg(&b1[c0]), bb1 = __ldg(&b1[c0 + 1]);
            float v00 = fmaxf(acc[mi][ni][0] + bb0, 0.f);
            float v01 = fmaxf(acc[mi][ni][1] + bb1, 0.f);
            float v10 = fmaxf(acc[mi][ni][2] + bb0, 0.f);
            float v11 = fmaxf(acc[mi][ni][3] + bb1, 0.f);
            int k2 = c0 >> 1;
            unsigned hi, lo;
            if (r0 < N_DET) {
                split_pair(v00, v01, hi, lo);
                Hh[(size_t)r0 * HID_P + k2] = hi;
                Hl[(size_t)r0 * HID_P + k2] = lo;
            }
            if (r1 < N_DET) {
                split_pair(v10, v11, hi, lo);
                Hh[(size_t)r1 * HID_P + k2] = hi;
                Hl[(size_t)r1 * HID_P + k2] = lo;
            }
        }
    }
}

// ---------------------------------------------------------------------------
// gemm2: T = H @ W2 + b2 -> fp16 tables g_S16 / g_O16.  grid (2, 157, 2)
// ---------------------------------------------------------------------------
__global__ __launch_bounds__(256, 3)
void gemm2(const float* __restrict__ b2s, const float* __restrict__ b2o)
{
    extern __shared__ unsigned sm[];
    unsigned* SA_hi = sm;
    unsigned* SA_lo = SA_hi + 2 * SA_BUF;
    unsigned* SB_hi = SA_lo + 2 * SA_BUF;
    unsigned* SB_lo = SB_hi + 2 * SB_BUF;

    const int tid = threadIdx.x, warp = tid >> 5, lane = tid & 31;
    const int g = lane >> 2, t = lane & 3;
    const int wm = warp >> 1, wn = warp & 1;
    const int n0 = blockIdx.x * 64;
    const int row0 = blockIdx.y * 128;
    const int net = blockIdx.z;

    const unsigned* __restrict__ Ah = g_Hp_hi[net];
    const unsigned* __restrict__ Al = g_Hp_lo[net];
    const ushort_t* __restrict__ Wh = g_W2e_hi[net];
    const ushort_t* __restrict__ Wl = g_W2e_lo[net];
    const float* __restrict__ b2 = net ? b2o : b2s;
    __half* __restrict__ out = net ? g_O16 : g_S16;

    const int lrow = tid >> 2, lcol = (tid & 3) * 4;
    int ga0 = row0 + lrow;      if (ga0 >= N_DET) ga0 = N_DET - 1;
    int ga1 = row0 + lrow + 64; if (ga1 >= N_DET) ga1 = N_DET - 1;
    const int brow = tid >> 3, bchunk = (tid & 7) * 8;

#define LOAD2(s, buf) do {                                                        \
        size_t o0 = (size_t)ga0 * HID_P + (s) * 16 + lcol;                        \
        size_t o1 = (size_t)ga1 * HID_P + (s) * 16 + lcol;                        \
        unsigned* dh = SA_hi + (buf) * SA_BUF;                                    \
        unsigned* dl = SA_lo + (buf) * SA_BUF;                                    \
        cp16(&dh[lrow * 20 + lcol], &Ah[o0]);                                     \
        cp16(&dh[(lrow + 64) * 20 + lcol], &Ah[o1]);                              \
        cp16(&dl[lrow * 20 + lcol], &Al[o0]);                                     \
        cp16(&dl[(lrow + 64) * 20 + lcol], &Al[o1]);                              \
        size_t ob = (size_t)((s) * 32 + brow) * OUT_DIM + n0 + bchunk;            \
        cp16((ushort_t*)(SB_hi + (buf) * SB_BUF) + brow * 72 + bchunk, &Wh[ob]);  \
        cp16((ushort_t*)(SB_lo + (buf) * SB_BUF) + brow * 72 + bchunk, &Wl[ob]);  \
        asm volatile("cp.async.commit_group;" ::: "memory");                      \
    } while (0)

    float acc[2][4][4];
#pragma unroll
    for (int mi = 0; mi < 2; mi++)
#pragma unroll
        for (int ni = 0; ni < 4; ni++)
#pragma unroll
            for (int r = 0; r < 4; r++) acc[mi][ni][r] = 0.f;

    LOAD2(0, 0);
    for (int s = 0; s < 8; s++) {
        if (s < 7) {
            LOAD2(s + 1, (s + 1) & 1);
            asm volatile("cp.async.wait_group 1;" ::: "memory");
        } else {
            asm volatile("cp.async.wait_group 0;" ::: "memory");
        }
        __syncthreads();
        const unsigned* sa_h = SA_hi + (s & 1) * SA_BUF;
        const unsigned* sa_l = SA_lo + (s & 1) * SA_BUF;
        const unsigned* sb_h = SB_hi + (s & 1) * SB_BUF;
        const unsigned* sb_l = SB_lo + (s & 1) * SB_BUF;
        GEMM_COMPUTE(sa_h, sa_l, sb_h, sb_l)
        __syncthreads();
    }
#undef LOAD2

    // Output epilogue: fp16 table stores (half2 per register pair)
#pragma unroll
    for (int mi = 0; mi < 2; mi++) {
        int r0 = row0 + wm * 32 + mi * 16 + g;
        int r1 = r0 + 8;
#pragma unroll
        for (int ni = 0; ni < 4; ni++) {
            int c = n0 + wn * 32 + ni * 8 + 2 * t;
            float bb0 = __ldg(&b2[c]), bb1 = __ldg(&b2[c + 1]);
            if (r0 < N_DET)
                *reinterpret_cast<__half2*>(&out[(size_t)r0 * OUT_DIM + c]) =
                    __floats2half2_rn(acc[mi][ni][0] + bb0, acc[mi][ni][1] + bb1);
            if (r1 < N_DET)
                *reinterpret_cast<__half2*>(&out[(size_t)r1 * OUT_DIM + c]) =
                    __floats2half2_rn(acc[mi][ni][2] + bb0, acc[mi][ni][3] + bb1);
        }
    }
}

// ---------------------------------------------------------------------------
// Edge phase: 8 lanes per edge (4 edges per warp), fp16 tables.
// ---------------------------------------------------------------------------
__device__ __forceinline__ float dot2h(unsigned a, unsigned b)
{
    float2 fa = __half22float2(*reinterpret_cast<__half2*>(&a));
    float2 fb = __half22float2(*reinterpret_cast<__half2*>(&b));
    return fa.x * fb.x + fa.y * fb.y;
}

__global__ void __launch_bounds__(256)
edge_kernel(const void* __restrict__ einds, float* __restrict__ out, int nE)
{
    long long warp = (long long)((blockIdx.x * blockDim.x + threadIdx.x) >> 5);
    int lane = threadIdx.x & 31;
    int sub = lane >> 3;
    int l   = lane & 7;
    long long e = warp * 4 + sub;
    if (e >= nE) return;

    long long i1, i2;
    if (g_idx64) {
        const long long* E = (const long long*)einds;
        i1 = __ldg(&E[3 * e + 1]);
        i2 = __ldg(&E[3 * e + 2]);
    } else {
        const int* E = (const int*)einds;
        i1 = __ldg(&E[3 * e + 1]);
        i2 = __ldg(&E[3 * e + 2]);
    }

    const uint4* s = reinterpret_cast<const uint4*>(g_S16 + i1 * OUT_DIM);
    const uint4* o = reinterpret_cast<const uint4*>(g_O16 + i2 * OUT_DIM);

    uint4 a0 = s[l], a1 = s[l + 8];
    uint4 b0 = o[l], b1 = o[l + 8];

    float sum = dot2h(a0.x, b0.x) + dot2h(a0.y, b0.y)
              + dot2h(a0.z, b0.z) + dot2h(a0.w, b0.w)
              + dot2h(a1.x, b1.x) + dot2h(a1.y, b1.y)
              + dot2h(a1.z, b1.z) + dot2h(a1.w, b1.w);

    sum += __shfl_xor_sync(0xffffffffu, sum, 4);
    sum += __shfl_xor_sync(0xffffffffu, sum, 2);
    sum += __shfl_xor_sync(0xffffffffu, sum, 1);

    if (l == 0)
        out[e] = 1.f / (1.f + __expf(-sum));
}

extern "C" void kernel_launch(void* const* d_in, const int* in_sizes, int n_in,
                              void* d_out, int out_size)
{
    const float* X     = (const float*)d_in[0];
    const void*  E     = d_in[1];
    const float* Ws_w1 = (const float*)d_in[2];
    const float* Ws_b1 = (const float*)d_in[3];
    const float* Ws_w2 = (const float*)d_in[4];
    const float* Ws_b2 = (const float*)d_in[5];
    const float* Wo_w1 = (const float*)d_in[6];
    const float* Wo_b1 = (const float*)d_in[7];
    const float* Wo_w2 = (const float*)d_in[8];
    const float* Wo_b2 = (const float*)d_in[9];

    cudaFuncSetAttribute(gemm1, cudaFuncAttributeMaxDynamicSharedMemorySize,
                         G_SMEM_WORDS * 4);
    cudaFuncSetAttribute(gemm2, cudaFuncAttributeMaxDynamicSharedMemorySize,
                         G_SMEM_WORDS * 4);

    probe_dtype<<<1, 1>>>((const long long*)E);

    int nprep = PREP_XTOT + PREP_W1TOT + PREP_W2TOT;
    prep_all<<<(nprep + 255) / 256, 256>>>(X, Ws_w1, Wo_w1, Ws_w2, Wo_w2);

    dim3 g1(HID_DIM / 64, (N_DET + 127) / 128, 2);   // (4, 157, 2)
    gemm1<<<g1, 256, G_SMEM_WORDS * 4>>>(Ws_b1, Wo_b1);

    dim3 g2(OUT_DIM / 64, (N_DET + 127) / 128, 2);   // (2, 157, 2)
    gemm2<<<g2, 256, G_SMEM_WORDS * 4>>>(Ws_b2, Wo_b2);

    int nE = in_sizes[1] / 3;                        // 1,000,000
    long long totalWarps = ((long long)nE + 3) / 4;
    long long totalThreads = totalWarps * 32;
    int nThreads = 256;
    int nBlocks = (int)((totalThreads + nThreads - 1) / nThreads);
    edge_kernel<<<nBlocks, nThreads>>>(E, (float*)d_out, nE);
}